// round 9
// baseline (speedup 1.0000x reference)
#include <cuda_runtime.h>
#include <cstdint>

// RBF kernel, D=1 degenerate case:
//   out[b,i,j] = exp( -(x1[b,i] - x2[b,j])^2 / (2*scale^2) )
// B=4, N1=N2=8192. Output = 1.073 GB fp32 -> pure DRAM-write-drain bound.
//
// FINAL — frozen at the measured HW ceiling.
//   TI=8 x TJ=1024 tile, 256 threads, one float4 of x2 in registers/thread,
//   scalar x1 broadcast loads (L1-hot), coalesced default-cache STG.E.128,
//   grid (8,1024,4) = 32768 CTAs (HW work-stealing makes waves free).
//
// Ceiling evidence (8 rounds): this binary benched 143.84 / 144.74 / 143.87us
// across three runs (DRAM 89.2-90.0%, up to 7136 GB/s = 89.2% of spec, zero
// DRAM read traffic). Tested and rejected: TI=16 (neutral), .cs stores
// (neutral), STG.256 (-2%), persistent single-wave (-19%: loop-carried tile
// decode breaks store MLP). Residual ~10% DRAM idle = HBM write
// turnaround/refresh; no SM-side lever remains. MUFU/FMA/issue all <50%.

static constexpr int B  = 4;
static constexpr int N1 = 8192;
static constexpr int N2 = 8192;
static constexpr int TI = 8;
static constexpr int TJ = 1024;   // 256 threads * float4

__global__ __launch_bounds__(256, 8)
void rbf_kernel(const float* __restrict__ x1,
                const float* __restrict__ x2,
                const float* __restrict__ scale,
                float* __restrict__ out)
{
    const int tid = threadIdx.x;
    const int jb  = blockIdx.x;        // 0..N2/TJ-1  (8)
    const int it  = blockIdx.y;        // 0..N1/TI-1  (1024)
    const int b   = blockIdx.z;        // 0..B-1

    const int j  = jb * TJ + tid * 4;
    const int i0 = it * TI;

    // x2 chunk for this thread (registers); x2 is L2-resident (32KB/batch).
    const float4 v2 = *reinterpret_cast<const float4*>(x2 + (size_t)b * N2 + j);

    const float s = scale[0];
    const float c = -0.5f / (s * s);   // out = exp(c * d^2)

    const float* x1b = x1 + (size_t)b * N1 + i0;
    float* outb = out + ((size_t)b * N1 + i0) * (size_t)N2 + j;

#pragma unroll
    for (int r = 0; r < TI; ++r) {
        const float a = __ldg(x1b + r);   // uniform across block, L1-hot
        const float dx0 = a - v2.x;
        const float dx1 = a - v2.y;
        const float dx2 = a - v2.z;
        const float dx3 = a - v2.w;
        float4 o;
        o.x = __expf(c * dx0 * dx0);
        o.y = __expf(c * dx1 * dx1);
        o.z = __expf(c * dx2 * dx2);
        o.w = __expf(c * dx3 * dx3);
        *reinterpret_cast<float4*>(outb + (size_t)r * N2) = o;
    }
}

extern "C" void kernel_launch(void* const* d_in, const int* in_sizes, int n_in,
                              void* d_out, int out_size)
{
    const float* x1    = (const float*)d_in[0];
    const float* x2    = (const float*)d_in[1];
    const float* scale = (const float*)d_in[2];
    float* out         = (float*)d_out;

    dim3 grid(N2 / TJ, N1 / TI, B);   // (8, 1024, 4)
    rbf_kernel<<<grid, 256>>>(x1, x2, scale, out);
}

// round 10
// speedup vs baseline: 1.0060x; 1.0060x over previous
#include <cuda_runtime.h>
#include <cstdint>

// RBF kernel, D=1 degenerate case:
//   out[b,i,j] = exp( -(x1[b,i] - x2[b,j])^2 / (2*scale^2) )
// B=4, N1=N2=8192. Output = 1.073 GB fp32 -> pure DRAM-write-drain bound.
//
// R10 probe (last untested cache path): st.global.wt.v4.f32 write-through
// stores. Hypothesis: eviction-driven L2 writeback leaves the DRAM write
// queue bursty (fill->evict waves); write-through feeds it uniformly.
// Everything else identical to the frozen optimum (R2: TI=8 x TJ=1024,
// 256 thr, float4 x2 in regs, scalar x1 broadcast, grid (8,1024,4)).
// Tested & rejected so far: .cs (neutral), STG.256 (-2%), TI=16 (neutral),
// persistent single-wave (-19%). Predicted: neutral (143.5-145) most likely;
// upside 141-143 if writeback burstiness is real. Neutral => freeze R2.

static constexpr int B  = 4;
static constexpr int N1 = 8192;
static constexpr int N2 = 8192;
static constexpr int TI = 8;
static constexpr int TJ = 1024;   // 256 threads * float4

__global__ __launch_bounds__(256, 8)
void rbf_kernel(const float* __restrict__ x1,
                const float* __restrict__ x2,
                const float* __restrict__ scale,
                float* __restrict__ out)
{
    const int tid = threadIdx.x;
    const int jb  = blockIdx.x;        // 0..7
    const int it  = blockIdx.y;        // 0..1023
    const int b   = blockIdx.z;        // 0..3

    const int j  = jb * TJ + tid * 4;
    const int i0 = it * TI;

    // x2 chunk for this thread (registers); x2 is L2-resident (32KB/batch).
    const float4 v2 = *reinterpret_cast<const float4*>(x2 + (size_t)b * N2 + j);

    const float s = scale[0];
    const float c = -0.5f / (s * s);   // out = exp(c * d^2)

    const float* x1b = x1 + (size_t)b * N1 + i0;
    float* outb = out + ((size_t)b * N1 + i0) * (size_t)N2 + j;

#pragma unroll
    for (int r = 0; r < TI; ++r) {
        const float a = __ldg(x1b + r);   // uniform across block, L1-hot
        const float dx0 = a - v2.x;
        const float dx1 = a - v2.y;
        const float dx2 = a - v2.z;
        const float dx3 = a - v2.w;
        const float o0 = __expf(c * dx0 * dx0);
        const float o1 = __expf(c * dx1 * dx1);
        const float o2 = __expf(c * dx2 * dx2);
        const float o3 = __expf(c * dx3 * dx3);
        // Write-through 128-bit store: push sectors toward DRAM immediately,
        // keeping the write queue uniformly fed instead of eviction-bursty.
        asm volatile(
            "st.global.wt.v4.f32 [%0], {%1, %2, %3, %4};"
            :: "l"(outb + (size_t)r * N2),
               "f"(o0), "f"(o1), "f"(o2), "f"(o3)
            : "memory");
    }
}

extern "C" void kernel_launch(void* const* d_in, const int* in_sizes, int n_in,
                              void* d_out, int out_size)
{
    const float* x1    = (const float*)d_in[0];
    const float* x2    = (const float*)d_in[1];
    const float* scale = (const float*)d_in[2];
    float* out         = (float*)d_out;

    dim3 grid(N2 / TJ, N1 / TI, B);   // (8, 1024, 4)
    rbf_kernel<<<grid, 256>>>(x1, x2, scale, out);
}

// round 11
// speedup vs baseline: 1.0085x; 1.0025x over previous
#include <cuda_runtime.h>
#include <cstdint>

// RBF kernel, D=1 degenerate case:
//   out[b,i,j] = exp( -(x1[b,i] - x2[b,j])^2 / (2*scale^2) )
// B=4, N1=N2=8192. Output = 1.073 GB fp32 -> pure DRAM-write-drain bound.
//
// FINAL — frozen at the measured hardware ceiling (best run: 143.808us,
// DRAM 89.9%, 7129 GB/s = 89.1% of 8TB/s spec, zero DRAM read traffic).
//
// Config: TI=8 x TJ=1024 tile, 256 threads, one float4 of x2 in registers
// per thread, scalar x1 broadcast loads (L1-hot), coalesced 128-bit
// write-through stores, grid (8,1024,4) = 32768 CTAs (HW work-stealing
// makes multi-wave launch free).
//
// 10-round evidence: cache-ops default/.cs/.wt all identical (~143.8-144.7us);
// STG.256 -2%; TI=16 neutral; persistent single-wave -19% (loop-carried tile
// decode breaks store MLP). All passing variants pin dram__cycles_active at
// 89-90%; MUFU/FMA/issue <50%. Residual ~10% idle = HBM3e write
// turnaround/refresh — not recoverable from the SM side.

static constexpr int B  = 4;
static constexpr int N1 = 8192;
static constexpr int N2 = 8192;
static constexpr int TI = 8;
static constexpr int TJ = 1024;   // 256 threads * float4

__global__ __launch_bounds__(256, 8)
void rbf_kernel(const float* __restrict__ x1,
                const float* __restrict__ x2,
                const float* __restrict__ scale,
                float* __restrict__ out)
{
    const int tid = threadIdx.x;
    const int jb  = blockIdx.x;        // 0..7
    const int it  = blockIdx.y;        // 0..1023
    const int b   = blockIdx.z;        // 0..3

    const int j  = jb * TJ + tid * 4;
    const int i0 = it * TI;

    // x2 chunk for this thread (registers); x2 is L2-resident (32KB/batch).
    const float4 v2 = *reinterpret_cast<const float4*>(x2 + (size_t)b * N2 + j);

    const float s = scale[0];
    const float c = -0.5f / (s * s);   // out = exp(c * d^2)

    const float* x1b = x1 + (size_t)b * N1 + i0;
    float* outb = out + ((size_t)b * N1 + i0) * (size_t)N2 + j;

#pragma unroll
    for (int r = 0; r < TI; ++r) {
        const float a = __ldg(x1b + r);   // uniform across block, L1-hot
        const float dx0 = a - v2.x;
        const float dx1 = a - v2.y;
        const float dx2 = a - v2.z;
        const float dx3 = a - v2.w;
        const float o0 = __expf(c * dx0 * dx0);
        const float o1 = __expf(c * dx1 * dx1);
        const float o2 = __expf(c * dx2 * dx2);
        const float o3 = __expf(c * dx3 * dx3);
        asm volatile(
            "st.global.wt.v4.f32 [%0], {%1, %2, %3, %4};"
            :: "l"(outb + (size_t)r * N2),
               "f"(o0), "f"(o1), "f"(o2), "f"(o3)
            : "memory");
    }
}

extern "C" void kernel_launch(void* const* d_in, const int* in_sizes, int n_in,
                              void* d_out, int out_size)
{
    const float* x1    = (const float*)d_in[0];
    const float* x2    = (const float*)d_in[1];
    const float* scale = (const float*)d_in[2];
    float* out         = (float*)d_out;

    dim3 grid(N2 / TJ, N1 / TI, B);   // (8, 1024, 4)
    rbf_kernel<<<grid, 256>>>(x1, x2, scale, out);
}